// round 10
// baseline (speedup 1.0000x reference)
#include <cuda_runtime.h>
#include <cuda_bf16.h>
#include <cstdint>

// NCutsLoss, fused single kernel.
//   acc(b,k,h,w)   = sum_{m,n} padded[b,k,h+m,w+n] * weight[b,0,h,w,m,n]
//   assocA[b,k]    = sum_{h,w} acc * seg
//   assocV[b,k]    = sum_{h,w} sum_weight * seg
//   out[b]         = 8.0 - sum_k assocA/assocV
// B=16, K=8, H=W=128, WIN=9, padded 136x136.
//
// R10: thread = 2 pixels x ALL 8 k -> each weight read from smem ONCE,
//      amortized over k in registers. Weight staged per-warp via manual
//      coalesced LDG.128 + STS.128 (bounded register batches; no cp.async,
//      no block barriers in the pipeline). Pad tile bf16.
//      TH=8, 256 blocks x 256 threads.

#define BB   16
#define KK   8
#define HH   128
#define WW   128
#define WIN  9
#define WQ   (WIN * WIN)      // 81
#define PH   (HH + WIN - 1)   // 136
#define PW   (WW + WIN - 1)   // 136

#define TH   8                // h-rows per block
#define PROWS (TH + WIN - 1)  // 16 padded rows in tile
#define PLANE_E (PROWS * PW)  // 2176 bf16 elems per k-plane
#define PLANE_W (PLANE_E / 2) // 1088 32-bit words per k-plane
#define PW_W   (PW / 2)       // 68 words per row

#define CPX   64              // pixels per chunk
#define NCH   2               // chunks per row
#define CHUNK_F  (CPX * WQ)   // 5184 floats
#define CHUNK_F4 (CHUNK_F / 4)// 1296 float4

#define NWARP 8
#define NTHR  256

#define PAD_BYTES  (KK * PLANE_E * 2)        // 34,816
#define WB_BYTES   (NWARP * CHUNK_F * 4)     // 165,888
#define SMEM_BYTES (PAD_BYTES + WB_BYTES)    // 200,704

#define NTILES (HH / TH)      // 16
#define NBLOCKS (BB * NTILES) // 256

__device__ float    g_part[BB * NTILES * 16];
__device__ unsigned g_ctr = 0;

// bf16 pair extraction, exact
__device__ __forceinline__ float lo16(uint32_t u) { return __uint_as_float(u << 16); }
__device__ __forceinline__ float hi16(uint32_t u) { return __uint_as_float(u & 0xFFFF0000u); }

// Stage one 5184-float chunk (1296 f4) global->smem, warp-cooperative.
// Coalesced LDG.128 + STS.128, batched 8 f4 at a time (bounded registers).
__device__ __forceinline__ void stage_chunk(float4* slot, const float* src, int lane)
{
    const float4* s4 = reinterpret_cast<const float4*>(src);
    #pragma unroll
    for (int g = 0; g < 5; ++g) {
        float4 r[9];
        const int nb = (g == 4) ? 9 : 8;
        #pragma unroll
        for (int j = 0; j < 9; ++j) {
            if (j < nb) {
                int idx = (g * 8 + j) * 32 + lane;
                if (idx < CHUNK_F4) r[j] = s4[idx];
            }
        }
        #pragma unroll
        for (int j = 0; j < 9; ++j) {
            if (j < nb) {
                int idx = (g * 8 + j) * 32 + lane;
                if (idx < CHUNK_F4) slot[idx] = r[j];
            }
        }
    }
}

__global__ __launch_bounds__(NTHR)
void ncuts_fused_kernel(const float* __restrict__ seg,
                        const float* __restrict__ pad,
                        const float* __restrict__ wgt,
                        const float* __restrict__ sw,
                        float* __restrict__ out)
{
    extern __shared__ char smem_raw[];
    __nv_bfloat16* padsm = reinterpret_cast<__nv_bfloat16*>(smem_raw);
    const uint32_t* padw = reinterpret_cast<const uint32_t*>(smem_raw);   // word view
    float* wslots = reinterpret_cast<float*>(smem_raw + PAD_BYTES);

    const int b    = blockIdx.y;
    const int h0   = blockIdx.x * TH;
    const int tid  = threadIdx.x;           // 0..255
    const int lane = tid & 31;
    const int ty   = tid >> 5;              // warp = one h-row
    const int h    = h0 + ty;

    // This warp's weight row and private staging slot.
    const float* wrow = wgt + (((size_t)b * HH + h) * WW) * WQ;   // 128 * 324B
    float* slot = wslots + ty * CHUNK_F;

    // ---- Stage weight chunk 0 (coalesced LDG + dense STS) ----
    stage_chunk(reinterpret_cast<float4*>(slot), wrow, lane);

    // ---- Fill padded-seg tile as bf16 (block-cooperative, coalesced) ----
    #pragma unroll
    for (int kk = 0; kk < KK; ++kk) {
        const float4* src = reinterpret_cast<const float4*>(
            pad + ((size_t)(b * KK + kk) * PH + h0) * PW);
        __nv_bfloat16* dstp = padsm + kk * PLANE_E;
        for (int i = tid; i < PLANE_E / 4; i += NTHR) {
            float4 v = src[i];
            uint32_t p0, p1;
            asm("cvt.rn.bf16x2.f32 %0, %1, %2;" : "=r"(p0) : "f"(v.y), "f"(v.x));
            asm("cvt.rn.bf16x2.f32 %0, %1, %2;" : "=r"(p1) : "f"(v.w), "f"(v.z));
            *reinterpret_cast<uint2*>(dstp + i * 4) = make_uint2(p0, p1);
        }
    }
    __syncthreads();   // pad tile + chunk-0 slots visible

    float vA[KK], vV[KK];
    #pragma unroll
    for (int k = 0; k < KK; ++k) { vA[k] = 0.0f; vV[k] = 0.0f; }

    #pragma unroll 1
    for (int c = 0; c < NCH; ++c) {
        const int w0 = c * CPX + 2 * lane;        // this thread's 2 pixels
        const float* s0 = slot + (2 * lane) * WQ; // slice p=0 (p=1 at +81)

        float acc0[KK], acc1[KK];
        #pragma unroll
        for (int k = 0; k < KK; ++k) { acc0[k] = 0.0f; acc1[k] = 0.0f; }

        // word base into pad tile: elem = (ty+m)*PW + w0 (even), per k +PLANE_W
        const int wbase = ty * PW_W + (w0 >> 1);

        #pragma unroll 1
        for (int m = 0; m < WIN; ++m) {
            // weight taps for both slices (scalar LDS, read once, reused 8x)
            const float* p0 = s0 + 9 * m;
            float wv0[WIN], wv1[WIN];
            #pragma unroll
            for (int n = 0; n < WIN; ++n) { wv0[n] = p0[n]; wv1[n] = p0[WQ + n]; }

            const uint32_t* prow = padw + wbase + m * PW_W;
            #pragma unroll
            for (int k = 0; k < KK; ++k) {
                const uint32_t* pk = prow + k * PLANE_W;
                uint32_t u0 = pk[0], u1 = pk[1], u2 = pk[2], u3 = pk[3], u4 = pk[4];
                float v[10] = { lo16(u0), hi16(u0), lo16(u1), hi16(u1),
                                lo16(u2), hi16(u2), lo16(u3), hi16(u3),
                                lo16(u4), hi16(u4) };
                #pragma unroll
                for (int n = 0; n < WIN; ++n) {
                    acc0[k] = fmaf(v[n],     wv0[n], acc0[k]);
                    acc1[k] = fmaf(v[n + 1], wv1[n], acc1[k]);
                }
            }
        }

        // ---- Fold with seg / sum_weight (acc dead after this) ----
        float2 sw2 = *reinterpret_cast<const float2*>(
            sw + ((size_t)b * HH + h) * WW + w0);
        #pragma unroll
        for (int k = 0; k < KK; ++k) {
            float2 s2 = *reinterpret_cast<const float2*>(
                seg + (((size_t)(b * KK + k) * HH + h) * WW + w0));
            vA[k] = fmaf(acc0[k], s2.x, vA[k]);
            vA[k] = fmaf(acc1[k], s2.y, vA[k]);
            vV[k] = fmaf(sw2.x, s2.x, vV[k]);
            vV[k] = fmaf(sw2.y, s2.y, vV[k]);
        }

        __syncwarp();            // all lanes done reading the slot

        if (c + 1 < NCH) {       // stage next chunk into the (now free) slot
            stage_chunk(reinterpret_cast<float4*>(slot),
                        wrow + (size_t)(c + 1) * CHUNK_F, lane);
            __syncwarp();        // cross-lane STS visibility
        }
    }

    // ---- Warp reduction over 32 lanes (all lanes hold all 8 k) ----
    #pragma unroll
    for (int off = 16; off > 0; off >>= 1) {
        #pragma unroll
        for (int k = 0; k < KK; ++k) {
            vA[k] += __shfl_xor_sync(0xFFFFFFFFu, vA[k], off);
            vV[k] += __shfl_xor_sync(0xFFFFFFFFu, vV[k], off);
        }
    }

    __shared__ float sred[NWARP][16];   // [warp=row][0..7 A_k, 8..15 V_k]
    if (lane == 0) {
        #pragma unroll
        for (int k = 0; k < KK; ++k) {
            sred[ty][k]     = vA[k];
            sred[ty][8 + k] = vV[k];
        }
    }
    __syncthreads();
    if (tid < 16) {
        float s = 0.0f;
        #pragma unroll
        for (int wrp = 0; wrp < NWARP; ++wrp)
            s += sred[wrp][tid];
        g_part[(b * NTILES + blockIdx.x) * 16 + tid] = s;
        __threadfence();             // publish partials
    }
    __syncthreads();

    // ---- Last-block finalize (deterministic fixed-order sums) ----
    __shared__ unsigned s_last;
    __shared__ float fin[BB * 16];
    if (tid == 0) {
        unsigned old = atomicAdd(&g_ctr, 1u);
        s_last = (old == NBLOCKS - 1) ? 1u : 0u;
    }
    __syncthreads();
    if (s_last) {
        __threadfence();
        {
            const int bb = tid >> 4, slot_i = tid & 15;   // 256 threads = 16x16
            float s = 0.0f;
            #pragma unroll
            for (int ht = 0; ht < NTILES; ++ht)
                s += g_part[(bb * NTILES + ht) * 16 + slot_i];
            fin[tid] = s;
        }
        __syncthreads();
        if (tid < BB) {
            float assoc = 0.0f;
            #pragma unroll
            for (int kk = 0; kk < KK; ++kk)
                assoc += fin[tid * 16 + kk] / fin[tid * 16 + 8 + kk];
            out[tid] = 8.0f - assoc;
        }
        if (tid == 0) g_ctr = 0;     // reset for next graph replay
    }
}

extern "C" void kernel_launch(void* const* d_in, const int* in_sizes, int n_in,
                              void* d_out, int out_size)
{
    const float *seg = nullptr, *pad = nullptr, *wgt = nullptr, *sw = nullptr;
    for (int i = 0; i < n_in; ++i) {
        int sz = in_sizes[i];
        if      (sz == BB * KK * HH * WW)        seg = (const float*)d_in[i];
        else if (sz == BB * KK * PH * PW)        pad = (const float*)d_in[i];
        else if (sz == BB * HH * WW * WQ)        wgt = (const float*)d_in[i];
        else if (sz == BB * HH * WW)             sw  = (const float*)d_in[i];
    }
    float* out = (float*)d_out;

    cudaFuncSetAttribute(ncuts_fused_kernel,
                         cudaFuncAttributeMaxDynamicSharedMemorySize, SMEM_BYTES);

    dim3 grid(NTILES, BB);     // 16 x 16 = 256 blocks
    ncuts_fused_kernel<<<grid, NTHR, SMEM_BYTES>>>(seg, pad, wgt, sw, out);
}

// round 11
// speedup vs baseline: 1.4668x; 1.4668x over previous
#include <cuda_runtime.h>
#include <cuda_bf16.h>
#include <cstdint>

// NCutsLoss, fused single kernel.
//   acc(b,k,h,w)   = sum_{m,n} padded[b,k,h+m,w+n] * weight[b,0,h,w,m,n]
//   assocA[b,k]    = sum_{h,w} acc * seg
//   assocV[b,k]    = sum_{h,w} sum_weight * seg
//   out[b]         = 8.0 - sum_k assocA/assocV
// B=16, K=8, H=W=128, WIN=9, padded 136x136.
//
// R11: R10's compute mapping (thread = 2 px x ALL 8 k; weight read from smem
//      once, amortized over k) in R4's launch shape (512 thr, TH=16,
//      128 blocks = one wave, 16 warps/SM). Enabled by staging weights in
//      smem as bf16 (halves slot size). Pad tile bf16. Manual coalesced
//      LDG.128 + cvt + STS.64 staging; warp-private slots; __syncwarp only.

#define BB   16
#define KK   8
#define HH   128
#define WW   128
#define WIN  9
#define WQ   (WIN * WIN)      // 81
#define PH   (HH + WIN - 1)   // 136
#define PW   (WW + WIN - 1)   // 136

#define TH   16               // h-rows per block (one per warp)
#define PROWS (TH + WIN - 1)  // 24 padded rows in tile
#define PLANE_E (PROWS * PW)  // 3264 bf16 elems per k-plane
#define PLANE_W (PLANE_E / 2) // 1632 words per k-plane
#define PW_W   (PW / 2)       // 68 words per row

#define CPX   64              // pixels per chunk
#define NCH   2               // chunks per row
#define CHUNK_F  (CPX * WQ)   // 5184 weight floats per chunk
#define CHUNK_F4 (CHUNK_F / 4)// 1296 float4
#define SLOT_W   (CHUNK_F / 2)// 2592 words (bf16 storage)

#define NWARP 16
#define NTHR  512

#define PAD_BYTES  (KK * PLANE_E * 2)        // 52,224
#define WB_BYTES   (NWARP * SLOT_W * 4)      // 165,888
#define SMEM_BYTES (PAD_BYTES + WB_BYTES)    // 218,112

#define NTILES (HH / TH)      // 8
#define NBLOCKS (BB * NTILES) // 128

__device__ float    g_part[BB * NTILES * 16];
__device__ unsigned g_ctr = 0;

// bf16 pair extraction, exact
__device__ __forceinline__ float lo16(uint32_t u) { return __uint_as_float(u << 16); }
__device__ __forceinline__ float hi16(uint32_t u) { return __uint_as_float(u & 0xFFFF0000u); }

// Extract 9 consecutive bf16 elems from 5 words given compile-time phase.
// phase 0: start at lo of w[0]; phase 1: start at hi of w[0].
template <int PHASE>
__device__ __forceinline__ void extract9(const uint32_t w[5], float e[9])
{
    if (PHASE == 0) {
        e[0] = lo16(w[0]); e[1] = hi16(w[0]);
        e[2] = lo16(w[1]); e[3] = hi16(w[1]);
        e[4] = lo16(w[2]); e[5] = hi16(w[2]);
        e[6] = lo16(w[3]); e[7] = hi16(w[3]);
        e[8] = lo16(w[4]);
    } else {
        e[0] = hi16(w[0]);
        e[1] = lo16(w[1]); e[2] = hi16(w[1]);
        e[3] = lo16(w[2]); e[4] = hi16(w[2]);
        e[5] = lo16(w[3]); e[6] = hi16(w[3]);
        e[7] = lo16(w[4]); e[8] = hi16(w[4]);
    }
}

// Stage one 5184-float weight chunk global->smem as bf16, warp-cooperative.
// Coalesced LDG.128 + cvt + STS.64 in bounded register batches.
__device__ __forceinline__ void stage_chunk_bf16(uint32_t* slotw, const float* src, int lane)
{
    const float4* s4 = reinterpret_cast<const float4*>(src);
    #pragma unroll
    for (int g = 0; g < 5; ++g) {
        float4 r[9];
        const int nb = (g == 4) ? 9 : 8;
        #pragma unroll
        for (int j = 0; j < 9; ++j) {
            if (j < nb) {
                int idx = (g * 8 + j) * 32 + lane;
                if (idx < CHUNK_F4) r[j] = s4[idx];
            }
        }
        #pragma unroll
        for (int j = 0; j < 9; ++j) {
            if (j < nb) {
                int idx = (g * 8 + j) * 32 + lane;
                if (idx < CHUNK_F4) {
                    uint32_t p0, p1;
                    asm("cvt.rn.bf16x2.f32 %0, %1, %2;" : "=r"(p0) : "f"(r[j].y), "f"(r[j].x));
                    asm("cvt.rn.bf16x2.f32 %0, %1, %2;" : "=r"(p1) : "f"(r[j].w), "f"(r[j].z));
                    *reinterpret_cast<uint2*>(slotw + idx * 2) = make_uint2(p0, p1);
                }
            }
        }
    }
}

__global__ __launch_bounds__(NTHR, 1)
void ncuts_fused_kernel(const float* __restrict__ seg,
                        const float* __restrict__ pad,
                        const float* __restrict__ wgt,
                        const float* __restrict__ sw,
                        float* __restrict__ out)
{
    extern __shared__ char smem_raw[];
    __nv_bfloat16* padsm = reinterpret_cast<__nv_bfloat16*>(smem_raw);
    const uint32_t* padw = reinterpret_cast<const uint32_t*>(smem_raw);   // word view
    uint32_t* wslots = reinterpret_cast<uint32_t*>(smem_raw + PAD_BYTES);

    const int b    = blockIdx.y;
    const int h0   = blockIdx.x * TH;
    const int tid  = threadIdx.x;           // 0..511
    const int lane = tid & 31;
    const int ty   = tid >> 5;              // warp = one h-row
    const int h    = h0 + ty;

    // This warp's weight row (128 px * 324B) and private bf16 slot.
    const float* wrow = wgt + (((size_t)b * HH + h) * WW) * WQ;
    uint32_t* slotw = wslots + ty * SLOT_W;

    // ---- Stage weight chunk 0 ----
    stage_chunk_bf16(slotw, wrow, lane);

    // ---- Fill padded-seg tile as bf16 (block-cooperative, coalesced) ----
    #pragma unroll
    for (int kk = 0; kk < KK; ++kk) {
        const float4* src = reinterpret_cast<const float4*>(
            pad + ((size_t)(b * KK + kk) * PH + h0) * PW);
        __nv_bfloat16* dstp = padsm + kk * PLANE_E;
        for (int i = tid; i < PLANE_E / 4; i += NTHR) {
            float4 v = src[i];
            uint32_t p0, p1;
            asm("cvt.rn.bf16x2.f32 %0, %1, %2;" : "=r"(p0) : "f"(v.y), "f"(v.x));
            asm("cvt.rn.bf16x2.f32 %0, %1, %2;" : "=r"(p1) : "f"(v.w), "f"(v.z));
            *reinterpret_cast<uint2*>(dstp + i * 4) = make_uint2(p0, p1);
        }
    }
    __syncthreads();   // pad tile visible to all warps

    float vA[KK], vV[KK];
    #pragma unroll
    for (int k = 0; k < KK; ++k) { vA[k] = 0.0f; vV[k] = 0.0f; }

    #pragma unroll 1
    for (int c = 0; c < NCH; ++c) {
        __syncwarp();            // slot STS (cross-lane) visible to this warp

        const int w0 = c * CPX + 2 * lane;           // this thread's 2 pixels
        // thread's weight region: 2 slices x 81 bf16, base elem 162*lane (even)
        const uint32_t* ws = slotw + 81 * lane;      // 81 words per thread

        float acc0[KK], acc1[KK];
        #pragma unroll
        for (int k = 0; k < KK; ++k) { acc0[k] = 0.0f; acc1[k] = 0.0f; }

        // pad word base: elem = ty*PW + w0 (even) -> word; per k add PLANE_W
        const int wbase = ty * PW_W + (w0 >> 1);

        #pragma unroll
        for (int m = 0; m < WIN; ++m) {
            // weight taps: slice0 elems 9m..9m+8, slice1 elems 81+9m..81+9m+8
            const int s0e = 9 * m;                   // parity = m&1 (compile-time)
            const int s1e = 81 + 9 * m;              // opposite parity
            uint32_t a[5], bw[5];
            #pragma unroll
            for (int j = 0; j < 5; ++j) a[j]  = ws[(s0e >> 1) + j];
            #pragma unroll
            for (int j = 0; j < 5; ++j) bw[j] = ws[(s1e >> 1) + j];
            float wv0[9], wv1[9];
            if ((s0e & 1) == 0) { extract9<0>(a, wv0); extract9<1>(bw, wv1); }
            else                { extract9<1>(a, wv0); extract9<0>(bw, wv1); }

            const uint32_t* prow = padw + wbase + m * PW_W;
            #pragma unroll
            for (int k = 0; k < KK; ++k) {
                const uint32_t* pk = prow + k * PLANE_W;
                uint32_t u0 = pk[0], u1 = pk[1], u2 = pk[2], u3 = pk[3], u4 = pk[4];
                float v[10] = { lo16(u0), hi16(u0), lo16(u1), hi16(u1),
                                lo16(u2), hi16(u2), lo16(u3), hi16(u3),
                                lo16(u4), hi16(u4) };
                #pragma unroll
                for (int n = 0; n < WIN; ++n) {
                    acc0[k] = fmaf(v[n],     wv0[n], acc0[k]);
                    acc1[k] = fmaf(v[n + 1], wv1[n], acc1[k]);
                }
            }
        }

        // ---- Fold with seg / sum_weight (acc dead after this) ----
        float2 sw2 = *reinterpret_cast<const float2*>(
            sw + ((size_t)b * HH + h) * WW + w0);
        #pragma unroll
        for (int k = 0; k < KK; ++k) {
            float2 s2 = *reinterpret_cast<const float2*>(
                seg + (((size_t)(b * KK + k) * HH + h) * WW + w0));
            vA[k] = fmaf(acc0[k], s2.x, vA[k]);
            vA[k] = fmaf(acc1[k], s2.y, vA[k]);
            vV[k] = fmaf(sw2.x, s2.x, vV[k]);
            vV[k] = fmaf(sw2.y, s2.y, vV[k]);
        }

        __syncwarp();            // all lanes done reading the slot

        if (c + 1 < NCH)         // stage next chunk into the (now free) slot
            stage_chunk_bf16(slotw, wrow + (size_t)(c + 1) * CHUNK_F, lane);
    }

    // ---- Warp reduction over 32 lanes (all lanes hold all 8 k) ----
    #pragma unroll
    for (int off = 16; off > 0; off >>= 1) {
        #pragma unroll
        for (int k = 0; k < KK; ++k) {
            vA[k] += __shfl_xor_sync(0xFFFFFFFFu, vA[k], off);
            vV[k] += __shfl_xor_sync(0xFFFFFFFFu, vV[k], off);
        }
    }

    __shared__ float sred[NWARP][16];   // [warp=row][0..7 A_k, 8..15 V_k]
    if (lane == 0) {
        #pragma unroll
        for (int k = 0; k < KK; ++k) {
            sred[ty][k]     = vA[k];
            sred[ty][8 + k] = vV[k];
        }
    }
    __syncthreads();
    if (tid < 16) {
        float s = 0.0f;
        #pragma unroll
        for (int wrp = 0; wrp < NWARP; ++wrp)
            s += sred[wrp][tid];
        g_part[(b * NTILES + blockIdx.x) * 16 + tid] = s;
        __threadfence();             // publish partials
    }
    __syncthreads();

    // ---- Last-block finalize (deterministic fixed-order sums) ----
    __shared__ unsigned s_last;
    __shared__ float fin[BB * 16];
    if (tid == 0) {
        unsigned old = atomicAdd(&g_ctr, 1u);
        s_last = (old == NBLOCKS - 1) ? 1u : 0u;
    }
    __syncthreads();
    if (s_last) {
        __threadfence();
        if (tid < BB * 16) {
            const int bb = tid >> 4, slot_i = tid & 15;
            float s = 0.0f;
            #pragma unroll
            for (int ht = 0; ht < NTILES; ++ht)
                s += g_part[(bb * NTILES + ht) * 16 + slot_i];
            fin[tid] = s;
        }
        __syncthreads();
        if (tid < BB) {
            float assoc = 0.0f;
            #pragma unroll
            for (int kk = 0; kk < KK; ++kk)
                assoc += fin[tid * 16 + kk] / fin[tid * 16 + 8 + kk];
            out[tid] = 8.0f - assoc;
        }
        if (tid == 0) g_ctr = 0;     // reset for next graph replay
    }
}

extern "C" void kernel_launch(void* const* d_in, const int* in_sizes, int n_in,
                              void* d_out, int out_size)
{
    const float *seg = nullptr, *pad = nullptr, *wgt = nullptr, *sw = nullptr;
    for (int i = 0; i < n_in; ++i) {
        int sz = in_sizes[i];
        if      (sz == BB * KK * HH * WW)        seg = (const float*)d_in[i];
        else if (sz == BB * KK * PH * PW)        pad = (const float*)d_in[i];
        else if (sz == BB * HH * WW * WQ)        wgt = (const float*)d_in[i];
        else if (sz == BB * HH * WW)             sw  = (const float*)d_in[i];
    }
    float* out = (float*)d_out;

    cudaFuncSetAttribute(ncuts_fused_kernel,
                         cudaFuncAttributeMaxDynamicSharedMemorySize, SMEM_BYTES);

    dim3 grid(NTILES, BB);     // 8 x 16 = 128 blocks, one wave
    ncuts_fused_kernel<<<grid, NTHR, SMEM_BYTES>>>(seg, pad, wgt, sw, out);
}

// round 12
// speedup vs baseline: 1.5080x; 1.0281x over previous
#include <cuda_runtime.h>
#include <cuda_bf16.h>
#include <cstdint>

// NCutsLoss, fused single kernel.
//   acc(b,k,h,w)   = sum_{m,n} padded[b,k,h+m,w+n] * weight[b,0,h,w,m,n]
//   assocA[b,k]    = sum_{h,w} acc * seg
//   assocV[b,k]    = sum_{h,w} sum_weight * seg
//   out[b]         = 8.0 - sum_k assocA/assocV
// B=16, K=8, H=W=128, WIN=9, padded 136x136.
//
// R12: 1024 threads / 32 warps per block. Warp pair per h-row:
//      row = warp>>1, khalf = warp&1; thread = 2 px x 4 k.
//      Halves the per-thread dependency chain and doubles warps/SMSP
//      (8 vs 4) to cover LDS/extract stalls. bf16 pad tile + per-row
//      bf16 weight slots (shared by the warp pair, staged split).

#define BB   16
#define KK   8
#define HH   128
#define WW   128
#define WIN  9
#define WQ   (WIN * WIN)      // 81
#define PH   (HH + WIN - 1)   // 136
#define PW   (WW + WIN - 1)   // 136

#define TH   16               // h-rows per block
#define PROWS (TH + WIN - 1)  // 24 padded rows
#define PLANE_E (PROWS * PW)  // 3264 bf16 per k-plane
#define PLANE_W (PLANE_E / 2) // 1632 words per k-plane
#define PW_W   (PW / 2)       // 68 words per row

#define CPX   64              // pixels per chunk
#define NCH   2               // chunks per row
#define CHUNK_F  (CPX * WQ)   // 5184 weight floats per chunk
#define CHUNK_F4 (CHUNK_F / 4)// 1296 float4
#define HALF_F4  (CHUNK_F4/2) // 648 float4 per staging warp
#define SLOT_W   (CHUNK_F / 2)// 2592 words (bf16)

#define NWARP 32
#define NTHR  1024

#define PAD_BYTES  (KK * PLANE_E * 2)        // 52,224
#define WB_BYTES   (TH * SLOT_W * 4)         // 165,888 (one slot per row)
#define SMEM_BYTES (PAD_BYTES + WB_BYTES)    // 218,112

#define NTILES (HH / TH)      // 8
#define NBLOCKS (BB * NTILES) // 128

__device__ float    g_part[BB * NTILES * 16];
__device__ unsigned g_ctr = 0;

// bf16 pair extraction, exact
__device__ __forceinline__ float lo16(uint32_t u) { return __uint_as_float(u << 16); }
__device__ __forceinline__ float hi16(uint32_t u) { return __uint_as_float(u & 0xFFFF0000u); }

// Extract 9 consecutive bf16 elems from 5 words; PHASE = start parity.
template <int PHASE>
__device__ __forceinline__ void extract9(const uint32_t w[5], float e[9])
{
    if (PHASE == 0) {
        e[0] = lo16(w[0]); e[1] = hi16(w[0]);
        e[2] = lo16(w[1]); e[3] = hi16(w[1]);
        e[4] = lo16(w[2]); e[5] = hi16(w[2]);
        e[6] = lo16(w[3]); e[7] = hi16(w[3]);
        e[8] = lo16(w[4]);
    } else {
        e[0] = hi16(w[0]);
        e[1] = lo16(w[1]); e[2] = hi16(w[1]);
        e[3] = lo16(w[2]); e[4] = hi16(w[2]);
        e[5] = lo16(w[3]); e[6] = hi16(w[3]);
        e[7] = lo16(w[4]); e[8] = hi16(w[4]);
    }
}

// Stage HALF of a weight chunk (648 f4) global->smem bf16, warp-cooperative.
// half = 0 or 1 selects the f4 range. Coalesced LDG.128 + cvt + STS.64.
__device__ __forceinline__ void stage_half_bf16(uint32_t* slotw, const float* chunk_src,
                                                int half, int lane)
{
    const float4* s4 = reinterpret_cast<const float4*>(chunk_src);
    const int base = half * HALF_F4;                  // f4 offset
    #pragma unroll
    for (int g = 0; g < 6; ++g) {                     // 6*4 = 24 >= 21 rounds
        float4 r[4];
        #pragma unroll
        for (int j = 0; j < 4; ++j) {
            int loc = (g * 4 + j) * 32 + lane;
            if (loc < HALF_F4) r[j] = s4[base + loc];
        }
        #pragma unroll
        for (int j = 0; j < 4; ++j) {
            int loc = (g * 4 + j) * 32 + lane;
            if (loc < HALF_F4) {
                uint32_t p0, p1;
                asm("cvt.rn.bf16x2.f32 %0, %1, %2;" : "=r"(p0) : "f"(r[j].y), "f"(r[j].x));
                asm("cvt.rn.bf16x2.f32 %0, %1, %2;" : "=r"(p1) : "f"(r[j].w), "f"(r[j].z));
                *reinterpret_cast<uint2*>(slotw + (base + loc) * 2) = make_uint2(p0, p1);
            }
        }
    }
}

__global__ __launch_bounds__(NTHR, 1)
void ncuts_fused_kernel(const float* __restrict__ seg,
                        const float* __restrict__ pad,
                        const float* __restrict__ wgt,
                        const float* __restrict__ sw,
                        float* __restrict__ out)
{
    extern __shared__ char smem_raw[];
    __nv_bfloat16* padsm = reinterpret_cast<__nv_bfloat16*>(smem_raw);
    const uint32_t* padw = reinterpret_cast<const uint32_t*>(smem_raw);   // word view
    uint32_t* wslots = reinterpret_cast<uint32_t*>(smem_raw + PAD_BYTES);

    const int b    = blockIdx.y;
    const int h0   = blockIdx.x * TH;
    const int tid  = threadIdx.x;           // 0..1023
    const int lane = tid & 31;
    const int wrp  = tid >> 5;              // 0..31
    const int row  = wrp >> 1;              // h-row within tile (0..15)
    const int kh   = wrp & 1;               // k-half (0: k0..3, 1: k4..7)
    const int kbase = kh * 4;
    const int h    = h0 + row;

    // Row's weight base and shared slot (one per row, staged by the pair).
    const float* wrow = wgt + (((size_t)b * HH + h) * WW) * WQ;
    uint32_t* slotw = wslots + row * SLOT_W;

    // ---- Stage this warp's half of weight chunk 0 ----
    stage_half_bf16(slotw, wrow, kh, lane);

    // ---- Fill padded-seg tile as bf16 (block-cooperative, coalesced) ----
    #pragma unroll
    for (int kk = 0; kk < KK; ++kk) {
        const float4* src = reinterpret_cast<const float4*>(
            pad + ((size_t)(b * KK + kk) * PH + h0) * PW);
        __nv_bfloat16* dstp = padsm + kk * PLANE_E;
        for (int i = tid; i < PLANE_E / 4; i += NTHR) {
            float4 v = src[i];
            uint32_t p0, p1;
            asm("cvt.rn.bf16x2.f32 %0, %1, %2;" : "=r"(p0) : "f"(v.y), "f"(v.x));
            asm("cvt.rn.bf16x2.f32 %0, %1, %2;" : "=r"(p1) : "f"(v.w), "f"(v.z));
            *reinterpret_cast<uint2*>(dstp + i * 4) = make_uint2(p0, p1);
        }
    }
    __syncthreads();   // pad tile + chunk-0 slots visible

    float vA[4], vV[4];
    #pragma unroll
    for (int k = 0; k < 4; ++k) { vA[k] = 0.0f; vV[k] = 0.0f; }

    #pragma unroll 1
    for (int c = 0; c < NCH; ++c) {
        const int w0 = c * CPX + 2 * lane;           // this thread's 2 pixels
        const uint32_t* ws = slotw + 81 * lane;      // 2 slices (162 bf16), even base

        float acc0[4], acc1[4];
        #pragma unroll
        for (int k = 0; k < 4; ++k) { acc0[k] = 0.0f; acc1[k] = 0.0f; }

        const int wbase = row * PW_W + (w0 >> 1);

        #pragma unroll
        for (int m = 0; m < WIN; ++m) {
            const int s0e = 9 * m;                   // parity compile-time
            const int s1e = 81 + 9 * m;
            uint32_t a[5], bw[5];
            #pragma unroll
            for (int j = 0; j < 5; ++j) a[j]  = ws[(s0e >> 1) + j];
            #pragma unroll
            for (int j = 0; j < 5; ++j) bw[j] = ws[(s1e >> 1) + j];
            float wv0[9], wv1[9];
            if ((s0e & 1) == 0) { extract9<0>(a, wv0); extract9<1>(bw, wv1); }
            else                { extract9<1>(a, wv0); extract9<0>(bw, wv1); }

            const uint32_t* prow = padw + wbase + m * PW_W;
            #pragma unroll
            for (int k = 0; k < 4; ++k) {
                const uint32_t* pk = prow + (size_t)(kbase + k) * PLANE_W;
                uint32_t u0 = pk[0], u1 = pk[1], u2 = pk[2], u3 = pk[3], u4 = pk[4];
                float v[10] = { lo16(u0), hi16(u0), lo16(u1), hi16(u1),
                                lo16(u2), hi16(u2), lo16(u3), hi16(u3),
                                lo16(u4), hi16(u4) };
                #pragma unroll
                for (int n = 0; n < WIN; ++n) {
                    acc0[k] = fmaf(v[n],     wv0[n], acc0[k]);
                    acc1[k] = fmaf(v[n + 1], wv1[n], acc1[k]);
                }
            }
        }

        // ---- Fold with seg / sum_weight ----
        float2 sw2 = *reinterpret_cast<const float2*>(
            sw + ((size_t)b * HH + h) * WW + w0);
        #pragma unroll
        for (int k = 0; k < 4; ++k) {
            float2 s2 = *reinterpret_cast<const float2*>(
                seg + (((size_t)(b * KK + kbase + k) * HH + h) * WW + w0));
            vA[k] = fmaf(acc0[k], s2.x, vA[k]);
            vA[k] = fmaf(acc1[k], s2.y, vA[k]);
            vV[k] = fmaf(sw2.x, s2.x, vV[k]);
            vV[k] = fmaf(sw2.y, s2.y, vV[k]);
        }

        if (c + 1 < NCH) {
            __syncthreads();     // all readers of the slots are done
            stage_half_bf16(slotw, wrow + (size_t)(c + 1) * CHUNK_F, kh, lane);
            __syncthreads();     // new chunk visible
        }
    }

    // ---- Warp reduction over 32 lanes (each warp holds its 4 k) ----
    #pragma unroll
    for (int off = 16; off > 0; off >>= 1) {
        #pragma unroll
        for (int k = 0; k < 4; ++k) {
            vA[k] += __shfl_xor_sync(0xFFFFFFFFu, vA[k], off);
            vV[k] += __shfl_xor_sync(0xFFFFFFFFu, vV[k], off);
        }
    }

    __shared__ float sred[NWARP][8];   // [warp][0..3 A, 4..7 V]
    if (lane == 0) {
        #pragma unroll
        for (int k = 0; k < 4; ++k) {
            sred[wrp][k]     = vA[k];
            sred[wrp][4 + k] = vV[k];
        }
    }
    __syncthreads();
    if (tid < 16) {
        // slot: 0..7 = A_k, 8..15 = V_k
        const int kslot = tid & 7;
        const int half  = kslot >> 2;          // which warp of the pair
        const int idx   = (kslot & 3) + ((tid < 8) ? 0 : 4);
        float s = 0.0f;
        #pragma unroll
        for (int r = 0; r < TH; ++r)
            s += sred[2 * r + half][idx];
        g_part[(b * NTILES + blockIdx.x) * 16 + tid] = s;
        __threadfence();             // publish partials
    }
    __syncthreads();

    // ---- Last-block finalize (deterministic fixed-order sums) ----
    __shared__ unsigned s_last;
    __shared__ float fin[BB * 16];
    if (tid == 0) {
        unsigned old = atomicAdd(&g_ctr, 1u);
        s_last = (old == NBLOCKS - 1) ? 1u : 0u;
    }
    __syncthreads();
    if (s_last) {
        __threadfence();
        if (tid < BB * 16) {
            const int bb = tid >> 4, slot_i = tid & 15;
            float s = 0.0f;
            #pragma unroll
            for (int ht = 0; ht < NTILES; ++ht)
                s += g_part[(bb * NTILES + ht) * 16 + slot_i];
            fin[tid] = s;
        }
        __syncthreads();
        if (tid < BB) {
            float assoc = 0.0f;
            #pragma unroll
            for (int kk = 0; kk < KK; ++kk)
                assoc += fin[tid * 16 + kk] / fin[tid * 16 + 8 + kk];
            out[tid] = 8.0f - assoc;
        }
        if (tid == 0) g_ctr = 0;     // reset for next graph replay
    }
}

extern "C" void kernel_launch(void* const* d_in, const int* in_sizes, int n_in,
                              void* d_out, int out_size)
{
    const float *seg = nullptr, *pad = nullptr, *wgt = nullptr, *sw = nullptr;
    for (int i = 0; i < n_in; ++i) {
        int sz = in_sizes[i];
        if      (sz == BB * KK * HH * WW)        seg = (const float*)d_in[i];
        else if (sz == BB * KK * PH * PW)        pad = (const float*)d_in[i];
        else if (sz == BB * HH * WW * WQ)        wgt = (const float*)d_in[i];
        else if (sz == BB * HH * WW)             sw  = (const float*)d_in[i];
    }
    float* out = (float*)d_out;

    cudaFuncSetAttribute(ncuts_fused_kernel,
                         cudaFuncAttributeMaxDynamicSharedMemorySize, SMEM_BYTES);

    dim3 grid(NTILES, BB);     // 8 x 16 = 128 blocks, one wave
    ncuts_fused_kernel<<<grid, NTHR, SMEM_BYTES>>>(seg, pad, wgt, sw, out);
}

// round 13
// speedup vs baseline: 1.5452x; 1.0247x over previous
#include <cuda_runtime.h>
#include <cuda_bf16.h>
#include <cstdint>

// NCutsLoss, fused single kernel.
//   acc(b,k,h,w)   = sum_{m,n} padded[b,k,h+m,w+n] * weight[b,0,h,w,m,n]
//   assocA[b,k]    = sum_{h,w} acc * seg
//   assocV[b,k]    = sum_{h,w} sum_weight * seg
//   out[b]         = 8.0 - sum_k assocA/assocV
// B=16, K=8, H=W=128, WIN=9, padded 136x136.
//
// R13 = R12 (1024 thr / 32 warps; warp pair per h-row; thread = 2 px x 4 k;
//       bf16 pad tile + bf16 weight slots) with two stall fixes:
//       (1) chunk-transition sync via NAMED barriers (4 warps) instead of
//           block-wide __syncthreads — no 32-warp convoy;
//       (2) staging in batches of 8 f4 (3 groups, not 6) — halves the
//           serialized LDG-wait exposure per warp.

#define BB   16
#define KK   8
#define HH   128
#define WW   128
#define WIN  9
#define WQ   (WIN * WIN)      // 81
#define PH   (HH + WIN - 1)   // 136
#define PW   (WW + WIN - 1)   // 136

#define TH   16               // h-rows per block
#define PROWS (TH + WIN - 1)  // 24 padded rows
#define PLANE_E (PROWS * PW)  // 3264 bf16 per k-plane
#define PLANE_W (PLANE_E / 2) // 1632 words per k-plane
#define PW_W   (PW / 2)       // 68 words per row

#define CPX   64              // pixels per chunk
#define NCH   2               // chunks per row
#define CHUNK_F  (CPX * WQ)   // 5184 weight floats per chunk
#define CHUNK_F4 (CHUNK_F / 4)// 1296 float4
#define HALF_F4  (CHUNK_F4/2) // 648 float4 per staging warp
#define SLOT_W   (CHUNK_F / 2)// 2592 words (bf16)

#define NWARP 32
#define NTHR  1024

#define PAD_BYTES  (KK * PLANE_E * 2)        // 52,224
#define WB_BYTES   (TH * SLOT_W * 4)         // 165,888 (one slot per row)
#define SMEM_BYTES (PAD_BYTES + WB_BYTES)    // 218,112

#define NTILES (HH / TH)      // 8
#define NBLOCKS (BB * NTILES) // 128

__device__ float    g_part[BB * NTILES * 16];
__device__ unsigned g_ctr = 0;

// Pair sync: named barrier over the 4 warps of rows (r) and (r+8).
// IDs 8..15 — never collide with __syncthreads (barrier 0).
#define PAIR_BAR(row) \
    asm volatile("bar.sync %0, 128;" :: "r"(8 + ((row) & 7)) : "memory")

// bf16 pair extraction, exact
__device__ __forceinline__ float lo16(uint32_t u) { return __uint_as_float(u << 16); }
__device__ __forceinline__ float hi16(uint32_t u) { return __uint_as_float(u & 0xFFFF0000u); }

// Extract 9 consecutive bf16 elems from 5 words; PHASE = start parity.
template <int PHASE>
__device__ __forceinline__ void extract9(const uint32_t w[5], float e[9])
{
    if (PHASE == 0) {
        e[0] = lo16(w[0]); e[1] = hi16(w[0]);
        e[2] = lo16(w[1]); e[3] = hi16(w[1]);
        e[4] = lo16(w[2]); e[5] = hi16(w[2]);
        e[6] = lo16(w[3]); e[7] = hi16(w[3]);
        e[8] = lo16(w[4]);
    } else {
        e[0] = hi16(w[0]);
        e[1] = lo16(w[1]); e[2] = hi16(w[1]);
        e[3] = lo16(w[2]); e[4] = hi16(w[2]);
        e[5] = lo16(w[3]); e[6] = hi16(w[3]);
        e[7] = lo16(w[4]); e[8] = hi16(w[4]);
    }
}

// Stage HALF of a weight chunk (648 f4) global->smem bf16, warp-cooperative.
// Batches of 8 f4 (32 transient regs): 3 LDG-wait exposures, not 6.
__device__ __forceinline__ void stage_half_bf16(uint32_t* slotw, const float* chunk_src,
                                                int half, int lane)
{
    const float4* s4 = reinterpret_cast<const float4*>(chunk_src);
    const int base = half * HALF_F4;                  // f4 offset
    #pragma unroll
    for (int g = 0; g < 3; ++g) {                     // 8+8+5 = 21 rounds
        const int nb = (g == 2) ? 5 : 8;
        float4 r[8];
        #pragma unroll
        for (int j = 0; j < 8; ++j) {
            if (j < nb) {
                int loc = (g * 8 + j) * 32 + lane;
                if (loc < HALF_F4) r[j] = s4[base + loc];
            }
        }
        #pragma unroll
        for (int j = 0; j < 8; ++j) {
            if (j < nb) {
                int loc = (g * 8 + j) * 32 + lane;
                if (loc < HALF_F4) {
                    uint32_t p0, p1;
                    asm("cvt.rn.bf16x2.f32 %0, %1, %2;" : "=r"(p0) : "f"(r[j].y), "f"(r[j].x));
                    asm("cvt.rn.bf16x2.f32 %0, %1, %2;" : "=r"(p1) : "f"(r[j].w), "f"(r[j].z));
                    *reinterpret_cast<uint2*>(slotw + (base + loc) * 2) = make_uint2(p0, p1);
                }
            }
        }
    }
}

__global__ __launch_bounds__(NTHR, 1)
void ncuts_fused_kernel(const float* __restrict__ seg,
                        const float* __restrict__ pad,
                        const float* __restrict__ wgt,
                        const float* __restrict__ sw,
                        float* __restrict__ out)
{
    extern __shared__ char smem_raw[];
    __nv_bfloat16* padsm = reinterpret_cast<__nv_bfloat16*>(smem_raw);
    const uint32_t* padw = reinterpret_cast<const uint32_t*>(smem_raw);   // word view
    uint32_t* wslots = reinterpret_cast<uint32_t*>(smem_raw + PAD_BYTES);

    const int b    = blockIdx.y;
    const int h0   = blockIdx.x * TH;
    const int tid  = threadIdx.x;           // 0..1023
    const int lane = tid & 31;
    const int wrp  = tid >> 5;              // 0..31
    const int row  = wrp >> 1;              // h-row within tile (0..15)
    const int kh   = wrp & 1;               // k-half
    const int kbase = kh * 4;
    const int h    = h0 + row;

    // Row's weight base and shared slot (one per row, staged by the pair).
    const float* wrow = wgt + (((size_t)b * HH + h) * WW) * WQ;
    uint32_t* slotw = wslots + row * SLOT_W;

    // ---- Stage this warp's half of weight chunk 0 ----
    stage_half_bf16(slotw, wrow, kh, lane);

    // ---- Fill padded-seg tile as bf16 (block-cooperative, coalesced) ----
    #pragma unroll
    for (int kk = 0; kk < KK; ++kk) {
        const float4* src = reinterpret_cast<const float4*>(
            pad + ((size_t)(b * KK + kk) * PH + h0) * PW);
        __nv_bfloat16* dstp = padsm + kk * PLANE_E;
        for (int i = tid; i < PLANE_E / 4; i += NTHR) {
            float4 v = src[i];
            uint32_t p0, p1;
            asm("cvt.rn.bf16x2.f32 %0, %1, %2;" : "=r"(p0) : "f"(v.y), "f"(v.x));
            asm("cvt.rn.bf16x2.f32 %0, %1, %2;" : "=r"(p1) : "f"(v.w), "f"(v.z));
            *reinterpret_cast<uint2*>(dstp + i * 4) = make_uint2(p0, p1);
        }
    }
    __syncthreads();   // pad tile + chunk-0 slots visible to all

    float vA[4], vV[4];
    #pragma unroll
    for (int k = 0; k < 4; ++k) { vA[k] = 0.0f; vV[k] = 0.0f; }

    #pragma unroll 1
    for (int c = 0; c < NCH; ++c) {
        const int w0 = c * CPX + 2 * lane;           // this thread's 2 pixels
        const uint32_t* ws = slotw + 81 * lane;      // 2 slices (162 bf16)

        float acc0[4], acc1[4];
        #pragma unroll
        for (int k = 0; k < 4; ++k) { acc0[k] = 0.0f; acc1[k] = 0.0f; }

        const int wbase = row * PW_W + (w0 >> 1);

        #pragma unroll
        for (int m = 0; m < WIN; ++m) {
            const int s0e = 9 * m;                   // parity compile-time
            const int s1e = 81 + 9 * m;
            uint32_t a[5], bw[5];
            #pragma unroll
            for (int j = 0; j < 5; ++j) a[j]  = ws[(s0e >> 1) + j];
            #pragma unroll
            for (int j = 0; j < 5; ++j) bw[j] = ws[(s1e >> 1) + j];
            float wv0[9], wv1[9];
            if ((s0e & 1) == 0) { extract9<0>(a, wv0); extract9<1>(bw, wv1); }
            else                { extract9<1>(a, wv0); extract9<0>(bw, wv1); }

            const uint32_t* prow = padw + wbase + m * PW_W;
            #pragma unroll
            for (int k = 0; k < 4; ++k) {
                const uint32_t* pk = prow + (size_t)(kbase + k) * PLANE_W;
                uint32_t u0 = pk[0], u1 = pk[1], u2 = pk[2], u3 = pk[3], u4 = pk[4];
                float v[10] = { lo16(u0), hi16(u0), lo16(u1), hi16(u1),
                                lo16(u2), hi16(u2), lo16(u3), hi16(u3),
                                lo16(u4), hi16(u4) };
                #pragma unroll
                for (int n = 0; n < WIN; ++n) {
                    acc0[k] = fmaf(v[n],     wv0[n], acc0[k]);
                    acc1[k] = fmaf(v[n + 1], wv1[n], acc1[k]);
                }
            }
        }

        // ---- Fold with seg / sum_weight ----
        float2 sw2 = *reinterpret_cast<const float2*>(
            sw + ((size_t)b * HH + h) * WW + w0);
        #pragma unroll
        for (int k = 0; k < 4; ++k) {
            float2 s2 = *reinterpret_cast<const float2*>(
                seg + (((size_t)(b * KK + kbase + k) * HH + h) * WW + w0));
            vA[k] = fmaf(acc0[k], s2.x, vA[k]);
            vA[k] = fmaf(acc1[k], s2.y, vA[k]);
            vV[k] = fmaf(sw2.x, s2.x, vV[k]);
            vV[k] = fmaf(sw2.y, s2.y, vV[k]);
        }

        if (c + 1 < NCH) {
            PAIR_BAR(row);       // pair (and partner pair) done reading slots
            stage_half_bf16(slotw, wrow + (size_t)(c + 1) * CHUNK_F, kh, lane);
            PAIR_BAR(row);       // new chunk visible (bar.sync drains STS)
        }
    }

    // ---- Warp reduction over 32 lanes (each warp holds its 4 k) ----
    #pragma unroll
    for (int off = 16; off > 0; off >>= 1) {
        #pragma unroll
        for (int k = 0; k < 4; ++k) {
            vA[k] += __shfl_xor_sync(0xFFFFFFFFu, vA[k], off);
            vV[k] += __shfl_xor_sync(0xFFFFFFFFu, vV[k], off);
        }
    }

    __shared__ float sred[NWARP][8];   // [warp][0..3 A, 4..7 V]
    if (lane == 0) {
        #pragma unroll
        for (int k = 0; k < 4; ++k) {
            sred[wrp][k]     = vA[k];
            sred[wrp][4 + k] = vV[k];
        }
    }
    __syncthreads();
    if (tid < 16) {
        // slot: 0..7 = A_k, 8..15 = V_k
        const int kslot = tid & 7;
        const int half  = kslot >> 2;          // which warp of the pair
        const int idx   = (kslot & 3) + ((tid < 8) ? 0 : 4);
        float s = 0.0f;
        #pragma unroll
        for (int r = 0; r < TH; ++r)
            s += sred[2 * r + half][idx];
        g_part[(b * NTILES + blockIdx.x) * 16 + tid] = s;
        __threadfence();             // publish partials
    }
    __syncthreads();

    // ---- Last-block finalize (deterministic fixed-order sums) ----
    __shared__ unsigned s_last;
    __shared__ float fin[BB * 16];
    if (tid == 0) {
        unsigned old = atomicAdd(&g_ctr, 1u);
        s_last = (old == NBLOCKS - 1) ? 1u : 0u;
    }
    __syncthreads();
    if (s_last) {
        __threadfence();
        if (tid < BB * 16) {
            const int bb = tid >> 4, slot_i = tid & 15;
            float s = 0.0f;
            #pragma unroll
            for (int ht = 0; ht < NTILES; ++ht)
                s += g_part[(bb * NTILES + ht) * 16 + slot_i];
            fin[tid] = s;
        }
        __syncthreads();
        if (tid < BB) {
            float assoc = 0.0f;
            #pragma unroll
            for (int kk = 0; kk < KK; ++kk)
                assoc += fin[tid * 16 + kk] / fin[tid * 16 + 8 + kk];
            out[tid] = 8.0f - assoc;
        }
        if (tid == 0) g_ctr = 0;     // reset for next graph replay
    }
}

extern "C" void kernel_launch(void* const* d_in, const int* in_sizes, int n_in,
                              void* d_out, int out_size)
{
    const float *seg = nullptr, *pad = nullptr, *wgt = nullptr, *sw = nullptr;
    for (int i = 0; i < n_in; ++i) {
        int sz = in_sizes[i];
        if      (sz == BB * KK * HH * WW)        seg = (const float*)d_in[i];
        else if (sz == BB * KK * PH * PW)        pad = (const float*)d_in[i];
        else if (sz == BB * HH * WW * WQ)        wgt = (const float*)d_in[i];
        else if (sz == BB * HH * WW)             sw  = (const float*)d_in[i];
    }
    float* out = (float*)d_out;

    cudaFuncSetAttribute(ncuts_fused_kernel,
                         cudaFuncAttributeMaxDynamicSharedMemorySize, SMEM_BYTES);

    dim3 grid(NTILES, BB);     // 8 x 16 = 128 blocks, one wave
    ncuts_fused_kernel<<<grid, NTHR, SMEM_BYTES>>>(seg, pad, wgt, sw, out);
}